// round 3
// baseline (speedup 1.0000x reference)
#include <cuda_runtime.h>
#include <math.h>

#define S_LEN   2048
#define DMODEL  1024
#define NHEADS  16
#define DK      64
#define BATCH   2
#define NTOK    (BATCH * S_LEN)     // 4096
#define BHALL   (BATCH * NHEADS)    // 32

// ---------------- scratch (device globals; no allocation allowed) ----------
__device__ float g_Q[BHALL * DK * S_LEN];     // (bh, d, s)  dk-major
__device__ float g_K[BHALL * DK * S_LEN];     // (bh, d, s)  dk-major
__device__ float g_V[BHALL * S_LEN * DK];     // (bh, s, d)
__device__ float g_O[NTOK * DMODEL];          // token-major attention output
__device__ float g_cs[BHALL * S_LEN];
__device__ float g_sn[BHALL * S_LEN];

// ============================================================================
// SGEMM: C = A(MxK) @ B(KxN) + bias, 128x128 tiles, BK=16, 256 thr, 8x8 micro
// MODE 0: C[m*N + n]                       (token-major)
// MODE 1: C[(bh*S + s)*DK + d]             (head-major, for V)
// MODE 2: C[(bh*DK + d)*S + s]             (dk-major,  for Q/K)
// ============================================================================
#define BM 128
#define BN 128
#define BKK 16
#define LDA (BM + 4)
#define LDB (BN + 4)

template <int MODE>
__global__ void __launch_bounds__(256, 2) sgemm128(
    const float* __restrict__ A, const float* __restrict__ B,
    const float* __restrict__ bias, float* __restrict__ C,
    int M, int N, int K)
{
    __shared__ float At[2][BKK * LDA];
    __shared__ float Bs[2][BKK * LDB];

    const int tid = threadIdx.x;
    const int tx = tid & 15;
    const int ty = tid >> 4;
    const int m0 = blockIdx.y * BM;
    const int n0 = blockIdx.x * BN;

    // A tile: 128 rows x 16 cols = 512 float4 (each thread: 2)
    const int am0 = tid >> 2;            const int ak0 = (tid & 3) << 2;
    const int am1 = (tid + 256) >> 2;    const int ak1 = ((tid + 256) & 3) << 2;
    // B tile: 16 rows x 128 cols = 512 float4
    const int bk0 = tid >> 5;            const int bn0 = (tid & 31) << 2;
    const int bk1 = (tid + 256) >> 5;    const int bn1 = ((tid + 256) & 31) << 2;

    float4 ra0, ra1, rb0, rb1;

    // prologue: tile 0
    ra0 = *(const float4*)&A[(size_t)(m0 + am0) * K + ak0];
    ra1 = *(const float4*)&A[(size_t)(m0 + am1) * K + ak1];
    rb0 = *(const float4*)&B[(size_t)bk0 * N + n0 + bn0];
    rb1 = *(const float4*)&B[(size_t)bk1 * N + n0 + bn1];

    At[0][(ak0 + 0) * LDA + am0] = ra0.x;
    At[0][(ak0 + 1) * LDA + am0] = ra0.y;
    At[0][(ak0 + 2) * LDA + am0] = ra0.z;
    At[0][(ak0 + 3) * LDA + am0] = ra0.w;
    At[0][(ak1 + 0) * LDA + am1] = ra1.x;
    At[0][(ak1 + 1) * LDA + am1] = ra1.y;
    At[0][(ak1 + 2) * LDA + am1] = ra1.z;
    At[0][(ak1 + 3) * LDA + am1] = ra1.w;
    *(float4*)&Bs[0][bk0 * LDB + bn0] = rb0;
    *(float4*)&Bs[0][bk1 * LDB + bn1] = rb1;
    __syncthreads();

    float acc[8][8];
#pragma unroll
    for (int i = 0; i < 8; i++)
#pragma unroll
        for (int j = 0; j < 8; j++) acc[i][j] = 0.f;

    const int KT = K / BKK;
    for (int kt = 0; kt < KT; ++kt) {
        const int buf = kt & 1;
        if (kt + 1 < KT) {
            const int k0 = (kt + 1) * BKK;
            ra0 = *(const float4*)&A[(size_t)(m0 + am0) * K + k0 + ak0];
            ra1 = *(const float4*)&A[(size_t)(m0 + am1) * K + k0 + ak1];
            rb0 = *(const float4*)&B[(size_t)(k0 + bk0) * N + n0 + bn0];
            rb1 = *(const float4*)&B[(size_t)(k0 + bk1) * N + n0 + bn1];
        }
#pragma unroll
        for (int kk = 0; kk < BKK; ++kk) {
            float a[8], bb[8];
            *(float4*)&a[0]  = *(const float4*)&At[buf][kk * LDA + ty * 8];
            *(float4*)&a[4]  = *(const float4*)&At[buf][kk * LDA + ty * 8 + 4];
            *(float4*)&bb[0] = *(const float4*)&Bs[buf][kk * LDB + tx * 8];
            *(float4*)&bb[4] = *(const float4*)&Bs[buf][kk * LDB + tx * 8 + 4];
#pragma unroll
            for (int i = 0; i < 8; i++)
#pragma unroll
                for (int j = 0; j < 8; j++) acc[i][j] += a[i] * bb[j];
        }
        if (kt + 1 < KT) {
            const int nb = 1 - buf;
            At[nb][(ak0 + 0) * LDA + am0] = ra0.x;
            At[nb][(ak0 + 1) * LDA + am0] = ra0.y;
            At[nb][(ak0 + 2) * LDA + am0] = ra0.z;
            At[nb][(ak0 + 3) * LDA + am0] = ra0.w;
            At[nb][(ak1 + 0) * LDA + am1] = ra1.x;
            At[nb][(ak1 + 1) * LDA + am1] = ra1.y;
            At[nb][(ak1 + 2) * LDA + am1] = ra1.z;
            At[nb][(ak1 + 3) * LDA + am1] = ra1.w;
            *(float4*)&Bs[nb][bk0 * LDB + bn0] = rb0;
            *(float4*)&Bs[nb][bk1 * LDB + bn1] = rb1;
            __syncthreads();
        }
    }

    float bv[8];
#pragma unroll
    for (int j = 0; j < 8; j++) bv[j] = bias[n0 + tx * 8 + j];

#pragma unroll
    for (int i = 0; i < 8; i++) {
        const int m = m0 + ty * 8 + i;
        if (MODE == 0) {
            float4 o0, o1;
            o0.x = acc[i][0] + bv[0]; o0.y = acc[i][1] + bv[1];
            o0.z = acc[i][2] + bv[2]; o0.w = acc[i][3] + bv[3];
            o1.x = acc[i][4] + bv[4]; o1.y = acc[i][5] + bv[5];
            o1.z = acc[i][6] + bv[6]; o1.w = acc[i][7] + bv[7];
            *(float4*)&C[(size_t)m * N + n0 + tx * 8]     = o0;
            *(float4*)&C[(size_t)m * N + n0 + tx * 8 + 4] = o1;
        } else {
            const int b = m >> 11;          // m / 2048
            const int s = m & 2047;
#pragma unroll
            for (int j = 0; j < 8; j++) {
                const int n = n0 + tx * 8 + j;
                const int h = n >> 6, d = n & 63;
                const int bh = b * NHEADS + h;
                const float v = acc[i][j] + bv[j];
                if (MODE == 1)
                    C[((size_t)bh * S_LEN + s) * DK + d] = v;
                else
                    C[((size_t)bh * DK + d) * S_LEN + s] = v;
            }
        }
    }
}

// ============================================================================
// Phase kernel: phase = x @ Wp + bp ; cos/sin stored per (bh, s)
// One block (128 thr) per token; 16 heads x 8 partial threads each.
// ============================================================================
__global__ void __launch_bounds__(128) phase_kernel(
    const float* __restrict__ x, const float* __restrict__ Wp,
    const float* __restrict__ bp, float* __restrict__ cs, float* __restrict__ sn)
{
    __shared__ float xs[DMODEL];
    const int m = blockIdx.x;
    for (int i = threadIdx.x; i < DMODEL / 4; i += 128)
        *(float4*)&xs[i * 4] = *(const float4*)&x[(size_t)m * DMODEL + i * 4];
    __syncthreads();

    const int h = threadIdx.x >> 3;
    const int part = threadIdx.x & 7;
    float sum = 0.f;
    const int k0 = part * 128;
#pragma unroll 4
    for (int k = k0; k < k0 + 128; ++k) sum += xs[k] * Wp[k * NHEADS + h];
#pragma unroll
    for (int off = 4; off >= 1; off >>= 1)
        sum += __shfl_xor_sync(0xffffffffu, sum, off);

    if (part == 0) {
        const float ph = sum + bp[h];
        const int b = m >> 11, s = m & 2047;
        const int bh = b * NHEADS + h;
        float sv, cv;
        sincosf(ph, &sv, &cv);
        cs[bh * S_LEN + s] = cv;
        sn[bh * S_LEN + s] = sv;
    }
}

// ============================================================================
// Flash attention, fp32. TQ=128 queries x TK=128 keys per tile, dk=64.
// 256 thr: 16x16 grid; QK micro 8x8, PV micro 8x4. Rank-2 coherence epilogue.
// ============================================================================
#define TQ 128
#define TK 128
#define QT_OFF 0                       // Qt[64][132]
#define KT_OFF (64 * 132)              // Kt[64][132]
#define VS_OFF (KT_OFF + 64 * 132)     // Vs[128][68]
#define PS_OFF (VS_OFF + 128 * 68)     // Ps[128][132]
#define KC_OFF (PS_OFF + 128 * 132)    // kc[128]
#define KS_OFF (KC_OFF + 128)          // ks[128]
#define ATT_SMEM_FLOATS (KS_OFF + 128)
#define ATT_SMEM_BYTES (ATT_SMEM_FLOATS * 4)

__global__ void __launch_bounds__(256, 1) attn_kernel(
    const float* __restrict__ Q, const float* __restrict__ K,
    const float* __restrict__ V, const float* __restrict__ cs,
    const float* __restrict__ sn, const float* __restrict__ alpha,
    float* __restrict__ O)
{
    extern __shared__ float sm[];
    const int tid = threadIdx.x;
    const int tx = tid & 15;
    const int ty = tid >> 4;
    const int bh = blockIdx.y;
    const int q0 = blockIdx.x * TQ;
    const float scale = 0.125f;             // dk^-0.5
    const float alp = alpha[bh & (NHEADS - 1)];

    // Load Qt[k][r] (dk-major global -> coalesced rows)
#pragma unroll
    for (int i = 0; i < 8; i++) {
        const int idx = tid + i * 256;      // 0..2047
        const int k = idx >> 5;
        const int r4 = (idx & 31) << 2;
        *(float4*)&sm[QT_OFF + k * 132 + r4] =
            *(const float4*)&Q[((size_t)bh * DK + k) * S_LEN + q0 + r4];
    }

    float qc[8], qs[8];
#pragma unroll
    for (int i = 0; i < 8; i++) {
        const int r = ty * 8 + i;
        qc[i] = cs[bh * S_LEN + q0 + r];
        qs[i] = sn[bh * S_LEN + q0 + r];
    }

    float m_i[8], l_i[8], o_acc[8][4];
#pragma unroll
    for (int i = 0; i < 8; i++) {
        m_i[i] = -1e30f; l_i[i] = 0.f;
#pragma unroll
        for (int j = 0; j < 4; j++) o_acc[i][j] = 0.f;
    }

    for (int kt = 0; kt < S_LEN / TK; ++kt) {
        const int c0 = kt * TK;
        __syncthreads();   // prev iter's PV done (and Qt visible on kt=0 path below)

        // Load Kt[k][c]
#pragma unroll
        for (int i = 0; i < 8; i++) {
            const int idx = tid + i * 256;
            const int k = idx >> 5;
            const int c4 = (idx & 31) << 2;
            *(float4*)&sm[KT_OFF + k * 132 + c4] =
                *(const float4*)&K[((size_t)bh * DK + k) * S_LEN + c0 + c4];
        }
        // Load Vs[c][d]
#pragma unroll
        for (int i = 0; i < 8; i++) {
            const int idx = tid + i * 256;
            const int c = idx >> 4;
            const int d4 = (idx & 15) << 2;
            *(float4*)&sm[VS_OFF + c * 68 + d4] =
                *(const float4*)&V[((size_t)bh * S_LEN + c0 + c) * DK + d4];
        }
        if (tid < 128) {
            sm[KC_OFF + tid] = cs[bh * S_LEN + c0 + tid];
            sm[KS_OFF + tid] = sn[bh * S_LEN + c0 + tid];
        }
        __syncthreads();

        // ---- QK^T ----
        float acc[8][8];
#pragma unroll
        for (int i = 0; i < 8; i++)
#pragma unroll
            for (int j = 0; j < 8; j++) acc[i][j] = 0.f;

#pragma unroll 8
        for (int k = 0; k < DK; ++k) {
            float a[8], bb[8];
            *(float4*)&a[0]  = *(const float4*)&sm[QT_OFF + k * 132 + ty * 8];
            *(float4*)&a[4]  = *(const float4*)&sm[QT_OFF + k * 132 + ty * 8 + 4];
            *(float4*)&bb[0] = *(const float4*)&sm[KT_OFF + k * 132 + tx * 8];
            *(float4*)&bb[4] = *(const float4*)&sm[KT_OFF + k * 132 + tx * 8 + 4];
#pragma unroll
            for (int i = 0; i < 8; i++)
#pragma unroll
                for (int j = 0; j < 8; j++) acc[i][j] += a[i] * bb[j];
        }

        // ---- coherence + online softmax ----
        float kcv[8], ksv[8];
#pragma unroll
        for (int j = 0; j < 8; j++) {
            kcv[j] = sm[KC_OFF + tx * 8 + j];
            ksv[j] = sm[KS_OFF + tx * 8 + j];
        }

#pragma unroll
        for (int i = 0; i < 8; i++) {
            float rmax = -1e30f;
#pragma unroll
            for (int j = 0; j < 8; j++) {
                float sv = acc[i][j] * scale + alp * (qc[i] * kcv[j] + qs[i] * ksv[j]);
                acc[i][j] = sv;
                rmax = fmaxf(rmax, sv);
            }
#pragma unroll
            for (int off = 8; off >= 1; off >>= 1)
                rmax = fmaxf(rmax, __shfl_xor_sync(0xffffffffu, rmax, off));

            const float mnew = fmaxf(m_i[i], rmax);
            const float corr = __expf(m_i[i] - mnew);
            m_i[i] = mnew;
            float rsum = 0.f;
#pragma unroll
            for (int j = 0; j < 8; j++) {
                const float p = __expf(acc[i][j] - mnew);
                acc[i][j] = p;
                rsum += p;
            }
#pragma unroll
            for (int off = 8; off >= 1; off >>= 1)
                rsum += __shfl_xor_sync(0xffffffffu, rsum, off);
            l_i[i] = l_i[i] * corr + rsum;
#pragma unroll
            for (int j = 0; j < 4; j++) o_acc[i][j] *= corr;
        }

        // write P to shared (row-major, vectorized)
#pragma unroll
        for (int i = 0; i < 8; i++) {
            float4 p0, p1;
            p0.x = acc[i][0]; p0.y = acc[i][1]; p0.z = acc[i][2]; p0.w = acc[i][3];
            p1.x = acc[i][4]; p1.y = acc[i][5]; p1.z = acc[i][6]; p1.w = acc[i][7];
            *(float4*)&sm[PS_OFF + (ty * 8 + i) * 132 + tx * 8]     = p0;
            *(float4*)&sm[PS_OFF + (ty * 8 + i) * 132 + tx * 8 + 4] = p1;
        }
        __syncthreads();

        // ---- PV: o[r][d] += sum_j P[r][j] * V[j][d] ----
#pragma unroll 2
        for (int j = 0; j < TK; j += 4) {
            float4 v0 = *(const float4*)&sm[VS_OFF + (j + 0) * 68 + tx * 4];
            float4 v1 = *(const float4*)&sm[VS_OFF + (j + 1) * 68 + tx * 4];
            float4 v2 = *(const float4*)&sm[VS_OFF + (j + 2) * 68 + tx * 4];
            float4 v3 = *(const float4*)&sm[VS_OFF + (j + 3) * 68 + tx * 4];
#pragma unroll
            for (int i = 0; i < 8; i++) {
                const float4 p = *(const float4*)&sm[PS_OFF + (ty * 8 + i) * 132 + j];
                o_acc[i][0] += p.x * v0.x + p.y * v1.x + p.z * v2.x + p.w * v3.x;
                o_acc[i][1] += p.x * v0.y + p.y * v1.y + p.z * v2.y + p.w * v3.y;
                o_acc[i][2] += p.x * v0.z + p.y * v1.z + p.z * v2.z + p.w * v3.z;
                o_acc[i][3] += p.x * v0.w + p.y * v1.w + p.z * v2.w + p.w * v3.w;
            }
        }
    }

    // epilogue: token-major write
    const int b = bh >> 4, h = bh & 15;
#pragma unroll
    for (int i = 0; i < 8; i++) {
        const int r = ty * 8 + i;
        const float inv = 1.f / l_i[i];
        float4 ov;
        ov.x = o_acc[i][0] * inv; ov.y = o_acc[i][1] * inv;
        ov.z = o_acc[i][2] * inv; ov.w = o_acc[i][3] * inv;
        *(float4*)&O[((size_t)b * S_LEN + q0 + r) * DMODEL + h * DK + tx * 4] = ov;
    }
}

// ============================================================================
extern "C" void kernel_launch(void* const* d_in, const int* in_sizes, int n_in,
                              void* d_out, int out_size)
{
    const float* x     = (const float*)d_in[0];
    const float* Wq    = (const float*)d_in[1];
    const float* bq    = (const float*)d_in[2];
    const float* Wk    = (const float*)d_in[3];
    const float* bk    = (const float*)d_in[4];
    const float* Wv    = (const float*)d_in[5];
    const float* bv    = (const float*)d_in[6];
    const float* Wo    = (const float*)d_in[7];
    const float* bo    = (const float*)d_in[8];
    const float* Wp    = (const float*)d_in[9];
    const float* bp    = (const float*)d_in[10];
    const float* alpha = (const float*)d_in[11];
    float* out = (float*)d_out;

    float *pQ, *pK, *pV, *pO, *pc, *ps;
    cudaGetSymbolAddress((void**)&pQ, g_Q);
    cudaGetSymbolAddress((void**)&pK, g_K);
    cudaGetSymbolAddress((void**)&pV, g_V);
    cudaGetSymbolAddress((void**)&pO, g_O);
    cudaGetSymbolAddress((void**)&pc, g_cs);
    cudaGetSymbolAddress((void**)&ps, g_sn);

    dim3 g(DMODEL / BN, NTOK / BM);   // (8, 32)

    sgemm128<2><<<g, 256>>>(x, Wq, bq, pQ, NTOK, DMODEL, DMODEL);
    sgemm128<2><<<g, 256>>>(x, Wk, bk, pK, NTOK, DMODEL, DMODEL);
    sgemm128<1><<<g, 256>>>(x, Wv, bv, pV, NTOK, DMODEL, DMODEL);
    phase_kernel<<<NTOK, 128>>>(x, Wp, bp, pc, ps);

    cudaFuncSetAttribute(attn_kernel,
                         cudaFuncAttributeMaxDynamicSharedMemorySize,
                         ATT_SMEM_BYTES);
    attn_kernel<<<dim3(S_LEN / TQ, BHALL), 256, ATT_SMEM_BYTES>>>(
        pQ, pK, pV, pc, ps, alpha, pO);

    sgemm128<0><<<g, 256>>>(pO, Wo, bo, out, NTOK, DMODEL, DMODEL);
}